// round 11
// baseline (speedup 1.0000x reference)
#include <cuda_runtime.h>
#include <cuda_fp16.h>
#include <cstdint>
#include <cstddef>

// ---------------- Problem constants ----------------
#define B_   32
#define S_   2048
#define HLEN 1024
#define VLEN 1024
#define HID  1024

// ---------------- Scratch (static device globals; no allocs allowed) ------
// g_Vh: tiled layout. Tile (b, sblk 0..7, kt 0..15) = 256 rows x 64 cols fp16,
//       stored as the exact swizzled 32KB smem image, contiguous.
// g_Uh: tiled layout. Tile (nb 0..7, kt 0..15) = 128 rows x 64 cols fp16, 16KB.
__device__ __align__(16) __half g_Vh[(size_t)B_ * S_ * VLEN];   // 128 MB
__device__ __align__(16) __half g_Uh[(size_t)HID * VLEN];       // 2 MB
__device__ __align__(16) float  g_hp[B_ * HID];                 // h_proj + bias
__device__ __align__(16) float  g_e[B_ * S_];                   // e scores -> beta
__device__ __align__(16) float  g_part[8 * B_ * VLEN];          // out partials

// ---------------- Helpers ----------------
__device__ __forceinline__ uint32_t smem_u32(const void* p) {
    return (uint32_t)__cvta_generic_to_shared(p);
}

__device__ __forceinline__ void ldsm_x4(uint32_t* r, uint32_t addr) {
    asm volatile("ldmatrix.sync.aligned.m8n8.x4.shared.b16 {%0,%1,%2,%3},[%4];"
                 : "=r"(r[0]), "=r"(r[1]), "=r"(r[2]), "=r"(r[3]) : "r"(addr));
}

__device__ __forceinline__ void mma16816(float* c, const uint32_t* a, const uint32_t* b) {
    asm volatile(
        "mma.sync.aligned.m16n8k16.row.col.f32.f16.f16.f32 "
        "{%0,%1,%2,%3},{%4,%5,%6,%7},{%8,%9},{%0,%1,%2,%3};"
        : "+f"(c[0]), "+f"(c[1]), "+f"(c[2]), "+f"(c[3])
        : "r"(a[0]), "r"(a[1]), "r"(a[2]), "r"(a[3]), "r"(b[0]), "r"(b[1]));
}

#define MBARRIER_INIT(addr, cnt) \
    asm volatile("mbarrier.init.shared.b64 [%0], %1;" :: "r"(addr), "r"(cnt) : "memory")
#define MBARRIER_ARRIVE(addr) \
    asm volatile("mbarrier.arrive.shared.b64 _, [%0];" :: "r"(addr) : "memory")

__device__ __forceinline__ void mbar_wait_parity(uint32_t mbar, uint32_t parity) {
    uint32_t done;
    asm volatile(
        "{\n\t.reg .pred p;\n\t"
        "mbarrier.try_wait.parity.acquire.cta.shared::cta.b64 p, [%1], %2;\n\t"
        "selp.b32 %0, 1, 0, p;\n\t}"
        : "=r"(done) : "r"(mbar), "r"(parity) : "memory");
    if (!done) {
        asm volatile(
            "{\n\t.reg .pred P1;\n\t"
            "WL_%=:\n\t"
            "mbarrier.try_wait.parity.acquire.cta.shared::cta.b64 P1, [%0], %1, 0x989680;\n\t"
            "@P1 bra.uni WD_%=;\n\t"
            "bra.uni WL_%=;\n\t"
            "WD_%=:\n\t}"
            :: "r"(mbar), "r"(parity) : "memory");
    }
}

__device__ __forceinline__ void bulk_ld(uint32_t dst, const void* src, uint32_t bytes, uint32_t mbar) {
    asm volatile(
        "cp.async.bulk.shared::cluster.global.mbarrier::complete_tx::bytes [%0], [%1], %2, [%3];"
        :: "r"(dst), "l"(src), "r"(bytes), "r"(mbar) : "memory");
}

__device__ __forceinline__ float tanh_fast(float x) {
    float y; asm("tanh.approx.f32 %0, %1;" : "=f"(y) : "f"(x)); return y;
}

__device__ __forceinline__ uint32_t pack_h2(float x, float y) {
    __half2 h = __floats2half2_rn(x, y);
    return *reinterpret_cast<uint32_t*>(&h);
}

// ---------------- Kernel 1: fp32 -> tiled/swizzled fp16 (V and U merged) --
// blk < 4096: V tile (b*128 + sblk*16 + kt), 256x64. blk >= 4096: U tile 128x64.
__global__ void cvt_kernel(const float* __restrict__ V, const float* __restrict__ U) {
    const int blk = blockIdx.x;
    const int t = threadIdx.x;
    if (blk < 4096) {
        const int b  = blk >> 7;
        const int sb = (blk >> 4) & 7;
        const int kt = blk & 15;
        const float* src = V + ((size_t)b * S_ + sb * 256) * VLEN + kt * 64;
        char* dst = reinterpret_cast<char*>(g_Vh) + (((size_t)(b * 8 + sb) * 16 + kt) << 15);
        const int rowq = t >> 2;       // 0..63
        const int cq   = t & 3;        // 16-float column group
        #pragma unroll
        for (int p = 0; p < 4; ++p) {
            const int row = rowq + p * 64;
            const float4* s4 = reinterpret_cast<const float4*>(src + (size_t)row * VLEN + cq * 16);
            #pragma unroll
            for (int j = 0; j < 2; ++j) {
                const float4 f0 = s4[j * 2], f1 = s4[j * 2 + 1];
                uint4 hv;
                hv.x = pack_h2(f0.x, f0.y); hv.y = pack_h2(f0.z, f0.w);
                hv.z = pack_h2(f1.x, f1.y); hv.w = pack_h2(f1.z, f1.w);
                uint32_t off = (row << 7) + cq * 32 + j * 16;
                off ^= (off >> 3) & 0x70;
                *reinterpret_cast<uint4*>(dst + off) = hv;
            }
        }
    } else {
        const int ublk = blk - 4096;   // 0..127
        const int nb = ublk >> 4;
        const int kt = ublk & 15;
        const float* src = U + (size_t)(nb * 128) * VLEN + kt * 64;
        char* dst = reinterpret_cast<char*>(g_Uh) + ((size_t)ublk << 14);
        const int row = t >> 1;        // 0..127
        const int cq  = t & 1;         // 32-float column group
        const float4* s4 = reinterpret_cast<const float4*>(src + (size_t)row * VLEN + cq * 32);
        #pragma unroll
        for (int j = 0; j < 4; ++j) {
            const float4 f0 = s4[j * 2], f1 = s4[j * 2 + 1];
            uint4 hv;
            hv.x = pack_h2(f0.x, f0.y); hv.y = pack_h2(f0.z, f0.w);
            hv.z = pack_h2(f1.x, f1.y); hv.w = pack_h2(f1.z, f1.w);
            uint32_t off = (row << 7) + cq * 64 + j * 16;
            off ^= (off >> 3) & 0x70;
            *reinterpret_cast<uint4*>(dst + off) = hv;
        }
    }
}

// ---------------- Kernel 2: h_proj — h staged in smem, warp per d ---------
// grid 128 blocks x 256 threads. Block handles 8 d's; lane owns one batch b.
// smem: h[32][1025] padded (conflict-free: bank = (lane + v) & 31).
#define HP_STRIDE 1025
#define HP_SMEM (B_ * HP_STRIDE * 4)
__global__ void __launch_bounds__(256) hproj_kernel(const float* __restrict__ h,
                                                    const float* __restrict__ Ww,
                                                    const float* __restrict__ Wb) {
    extern __shared__ float sh[];
    const int tid = threadIdx.x;
    for (int i = tid; i < B_ * HLEN; i += 256)
        sh[(i >> 10) * HP_STRIDE + (i & 1023)] = h[i];
    __syncthreads();

    const int warp = tid >> 5, lane = tid & 31;
    const int d = blockIdx.x * 8 + warp;
    const float* wr = Ww + (size_t)d * HLEN;
    const float* hrow = sh + lane * HP_STRIDE;
    float acc = 0.f;
    #pragma unroll 8
    for (int v = 0; v < HLEN; ++v)
        acc += hrow[v] * __ldg(wr + v);
    g_hp[lane * HID + d] = acc + Wb[d];
}

// ---------------- Kernel 3: fused e = w·tanh(hp + V U^T) ----------------
// Bulk-DMA mbarrier pipeline, 4 stages. 512 threads (16 warps: 8(M) x 2(N)).
// Tile M=256(s), N=128(d), K=64. grid=(8, 32). hp/ww staged in smem.
#define NTILES 128
#define NSTAGE 4
#define STAGE_SZ 49152
#define SMEM_STAGE0 12288
#define E_SMEM (SMEM_STAGE0 + NSTAGE * STAGE_SZ)   // 208896

__global__ void __launch_bounds__(512, 1) e_kernel(const float* __restrict__ ww) {
    extern __shared__ char smem[];
    const uint32_t sbase = smem_u32(smem);
    float* e_red = reinterpret_cast<float*>(smem + 64);     // 256 floats
    float* sm_hp = reinterpret_cast<float*>(smem + 1088);   // 1024 floats
    float* sm_ww = reinterpret_cast<float*>(smem + 5184);   // 1024 floats

    const int tid  = threadIdx.x;
    const int lane = tid & 31;
    const int warp = tid >> 5;
    const int wm = warp & 7;     // 0..7 -> 32 rows each (256 total)
    const int wn = warp >> 3;    // 0..1 -> 64 cols each
    const int b  = blockIdx.y;
    const int sb = blockIdx.x;   // s-block of 256

    const uint32_t full0  = sbase;        // 4 x 8B
    const uint32_t empty0 = sbase + 32;   // 4 x 8B

    if (tid == 0) {
        #pragma unroll
        for (int s = 0; s < NSTAGE; s++) {
            MBARRIER_INIT(full0 + s * 8, 1);
            MBARRIER_INIT(empty0 + s * 8, 16);
        }
    }
    if (tid < 256) {
        e_red[tid] = 0.f;
        const float4 h4 = reinterpret_cast<const float4*>(g_hp + b * HID)[tid];
        reinterpret_cast<float4*>(sm_hp)[tid] = h4;
        const float4 w4 = reinterpret_cast<const float4*>(ww)[tid];
        reinterpret_cast<float4*>(sm_ww)[tid] = w4;
    }
    __syncthreads();

    const char* Ab = reinterpret_cast<const char*>(g_Vh) + (((size_t)(b * 8 + sb) * 16) << 15);
    const char* Bb = reinterpret_cast<const char*>(g_Uh);

    // ---- producer: single thread, 2 bulk copies per tile ----
    auto produce = [&](int c) {
        const int s = c & (NSTAGE - 1), r = c >> 2;
        if (r >= 1) mbar_wait_parity(empty0 + s * 8, (uint32_t)(r - 1) & 1);
        const uint32_t mb = full0 + s * 8;
        asm volatile("mbarrier.arrive.expect_tx.shared.b64 _, [%0], %1;"
                     :: "r"(mb), "r"(49152u) : "memory");
        const uint32_t dstA = sbase + SMEM_STAGE0 + s * STAGE_SZ;
        bulk_ld(dstA,         Ab + ((size_t)(c & 15) << 15), 32768u, mb);
        bulk_ld(dstA + 32768, Bb + ((size_t)((c >> 4) * 16 + (c & 15)) << 14), 16384u, mb);
    };

    if (tid == 0) { produce(0); produce(1); produce(2); }

    // ---- ldmatrix address precompute ----
    uint32_t abase[2], axor[2];
    #pragma unroll
    for (int mf = 0; mf < 2; ++mf) {
        const uint32_t row = wm * 32 + mf * 16 + (lane & 15);
        abase[mf] = row << 7;
        axor[mf]  = (row & 7) << 4;
    }
    const uint32_t acol0 = (lane >> 4) << 4;
    uint32_t bbase[4], bxor[4];
    #pragma unroll
    for (int nf2 = 0; nf2 < 4; ++nf2) {
        const uint32_t row = wn * 64 + nf2 * 16 + ((lane >> 4) << 3) + (lane & 7);
        bbase[nf2] = row << 7;
        bxor[nf2]  = (row & 7) << 4;
    }
    const uint32_t bcol0 = ((lane >> 3) & 1) << 4;

    float acc[2][8][4] = {};
    float e_part[4] = {0.f, 0.f, 0.f, 0.f};

    for (int t = 0; t < NTILES; ++t) {
        if (tid == 0 && t + 3 < NTILES) produce(t + 3);

        mbar_wait_parity(full0 + (t & 3) * 8, (uint32_t)(t >> 2) & 1);

        const uint32_t stg  = sbase + SMEM_STAGE0 + (t & 3) * STAGE_SZ;
        const uint32_t stgB = stg + 32768;

        #pragma unroll
        for (int ks = 0; ks < 4; ++ks) {
            const uint32_t kcol = (uint32_t)ks << 5;
            uint32_t a[2][4];
            #pragma unroll
            for (int mf = 0; mf < 2; ++mf)
                ldsm_x4(a[mf], stg + abase[mf] + ((kcol + acol0) ^ axor[mf]));
            uint32_t bb[4][4];
            #pragma unroll
            for (int nf2 = 0; nf2 < 4; ++nf2)
                ldsm_x4(bb[nf2], stgB + bbase[nf2] + ((kcol + bcol0) ^ bxor[nf2]));
            #pragma unroll
            for (int mf = 0; mf < 2; ++mf)
                #pragma unroll
                for (int nf = 0; nf < 8; ++nf)
                    mma16816(acc[mf][nf], a[mf], &bb[nf >> 1][(nf & 1) * 2]);
        }

        if (lane == 0) MBARRIER_ARRIVE(empty0 + (t & 3) * 8);

        if ((t & 15) == 15) {
            // ---- fold tanh + w_w dot on this 128-col n-block, reset acc ----
            const int n0 = (t >> 4) << 7;
            const int cb = (n0 + wn * 64) >> 1;  // float2 index base
            const float2* hp2 = reinterpret_cast<const float2*>(sm_hp);
            const float2* ww2 = reinterpret_cast<const float2*>(sm_ww);
            #pragma unroll
            for (int nf = 0; nf < 8; ++nf) {
                const int ci = cb + nf * 4 + (lane & 3);
                const float2 hh = hp2[ci];
                const float2 wv = ww2[ci];
                #pragma unroll
                for (int mf = 0; mf < 2; ++mf) {
                    e_part[mf * 2 + 0] += tanh_fast(acc[mf][nf][0] + hh.x) * wv.x
                                        + tanh_fast(acc[mf][nf][1] + hh.y) * wv.y;
                    e_part[mf * 2 + 1] += tanh_fast(acc[mf][nf][2] + hh.x) * wv.x
                                        + tanh_fast(acc[mf][nf][3] + hh.y) * wv.y;
                    acc[mf][nf][0] = 0.f; acc[mf][nf][1] = 0.f;
                    acc[mf][nf][2] = 0.f; acc[mf][nf][3] = 0.f;
                }
            }
        }
    }

    // reduce over the 4 lanes sharing each row
    #pragma unroll
    for (int i = 0; i < 4; i++) {
        e_part[i] += __shfl_xor_sync(0xffffffffu, e_part[i], 1);
        e_part[i] += __shfl_xor_sync(0xffffffffu, e_part[i], 2);
    }
    if ((lane & 3) == 0) {
        #pragma unroll
        for (int i = 0; i < 4; i++) {
            const int r = wm * 32 + (i >> 1) * 16 + (i & 1) * 8 + (lane >> 2);
            atomicAdd(&e_red[r], e_part[i]);
        }
    }
    __syncthreads();
    if (tid < 256)
        g_e[(size_t)b * S_ + sb * 256 + tid] = e_red[tid];
}

// ---------------- Kernel 4: softmax over S (in-place on g_e) -------------
__global__ void softmax_kernel() {
    int b = blockIdx.x;
    float* row = g_e + (size_t)b * S_;
    __shared__ float red[256];
    float m = -1e30f;
    for (int s = threadIdx.x; s < S_; s += 256) m = fmaxf(m, row[s]);
    red[threadIdx.x] = m; __syncthreads();
    for (int o = 128; o > 0; o >>= 1) {
        if (threadIdx.x < o) red[threadIdx.x] = fmaxf(red[threadIdx.x], red[threadIdx.x + o]);
        __syncthreads();
    }
    m = red[0]; __syncthreads();
    float sum = 0.f;
    for (int s = threadIdx.x; s < S_; s += 256) {
        float v = __expf(row[s] - m);
        row[s] = v;
        sum += v;
    }
    red[threadIdx.x] = sum; __syncthreads();
    for (int o = 128; o > 0; o >>= 1) {
        if (threadIdx.x < o) red[threadIdx.x] += red[threadIdx.x + o];
        __syncthreads();
    }
    float inv = 1.f / red[0];
    for (int s = threadIdx.x; s < S_; s += 256) row[s] *= inv;
}

// ---------------- Kernel 5: out partials (tiled fp16 V, 8 s-chunks) -------
// grid (2, B, 8), 256 threads; each thread owns one half2 column, one 256-row s-block.
__global__ void out_part_kernel() {
    const int vc = blockIdx.x, b = blockIdx.y, sblk = blockIdx.z;
    const int v2 = vc * 256 + threadIdx.x;     // half2 col 0..511
    const int kt = v2 >> 5;                    // 64-col tile index
    const uint32_t coff = (v2 & 31) << 2;
    const float* beta = g_e + (size_t)b * S_ + sblk * 256;
    const char* tile = reinterpret_cast<const char*>(g_Vh)
                     + (((size_t)(b * 8 + sblk) * 16 + kt) << 15);

    float ax = 0.f, ay = 0.f;
    #pragma unroll 8
    for (int r = 0; r < 256; ++r) {
        uint32_t off = (r << 7) + coff;
        off ^= (off >> 3) & 0x70;
        const float2 vv = __half22float2(*reinterpret_cast<const __half2*>(tile + off));
        const float bt = beta[r];
        ax += bt * vv.x;
        ay += bt * vv.y;
    }
    float2* dst = reinterpret_cast<float2*>(g_part) + ((size_t)sblk * B_ + b) * (VLEN / 2) + v2;
    *dst = make_float2(ax, ay);
}

// ---------------- Kernel 6: reduce partials --------------------------------
__global__ void out_reduce_kernel(float* __restrict__ out) {
    int i = blockIdx.x * 256 + threadIdx.x;
    const int stride = B_ * VLEN;
    float s = 0.f;
    #pragma unroll
    for (int c = 0; c < 8; ++c) s += g_part[(size_t)c * stride + i];
    out[i] = s;
}

// ---------------- Launch ----------------
extern "C" void kernel_launch(void* const* d_in, const int* in_sizes, int n_in,
                              void* d_out, int out_size) {
    const float* h   = (const float*)d_in[0];   // [B, HLEN]
    const float* V   = (const float*)d_in[1];   // [B, S, VLEN]
    const float* W_w = (const float*)d_in[2];   // [HID, HLEN]
    const float* W_b = (const float*)d_in[3];   // [HID]
    const float* U_w = (const float*)d_in[4];   // [HID, VLEN]
    const float* w_w = (const float*)d_in[5];   // [HID]
    float* out = (float*)d_out;                 // [B, VLEN]

    cudaFuncSetAttribute(e_kernel, cudaFuncAttributeMaxDynamicSharedMemorySize, E_SMEM);
    cudaFuncSetAttribute(hproj_kernel, cudaFuncAttributeMaxDynamicSharedMemorySize, HP_SMEM);

    // 1. fp32 -> tiled/swizzled fp16 (V + U in one launch)
    cvt_kernel<<<4096 + 128, 256>>>(V, U_w);
    // 2. h_proj (smem-staged h)
    hproj_kernel<<<128, 256, HP_SMEM>>>(h, W_w, W_b);
    // 3. fused e scores (bulk-DMA mbarrier pipelined HMMA, 4 stages)
    {
        dim3 grid(8, B_);
        e_kernel<<<grid, 512, E_SMEM>>>(w_w);
    }
    // 4. softmax
    softmax_kernel<<<B_, 256>>>();
    // 5. weighted sum partials (tiled fp16 V, 8 s-chunks)
    {
        dim3 grid(2, B_, 8);
        out_part_kernel<<<grid, 256>>>();
    }
    // 6. reduce
    out_reduce_kernel<<<(B_ * VLEN) / 256, 256>>>(out);
}

// round 12
// speedup vs baseline: 1.0954x; 1.0954x over previous
#include <cuda_runtime.h>
#include <cuda_fp16.h>
#include <cstdint>
#include <cstddef>

// ---------------- Problem constants ----------------
#define B_   32
#define S_   2048
#define HLEN 1024
#define VLEN 1024
#define HID  1024

// ---------------- Scratch (static device globals; no allocs allowed) ------
// g_Vh: tiled layout. Tile (b, sblk 0..7, kt 0..15) = 256 rows x 64 cols fp16,
//       stored as the exact swizzled 32KB smem image, contiguous.
// g_Uh: tiled layout. Tile (nb 0..7, kt 0..15) = 128 rows x 64 cols fp16, 16KB.
__device__ __align__(16) __half g_Vh[(size_t)B_ * S_ * VLEN];   // 128 MB
__device__ __align__(16) __half g_Uh[(size_t)HID * VLEN];       // 2 MB
__device__ __align__(16) float  g_hp[B_ * HID];                 // h_proj + bias
__device__ __align__(16) float  g_e[B_ * S_];                   // e scores -> beta
__device__ __align__(16) float  g_part[8 * B_ * VLEN];          // out partials

// ---------------- Helpers ----------------
__device__ __forceinline__ uint32_t smem_u32(const void* p) {
    return (uint32_t)__cvta_generic_to_shared(p);
}

__device__ __forceinline__ void ldsm_x4(uint32_t* r, uint32_t addr) {
    asm volatile("ldmatrix.sync.aligned.m8n8.x4.shared.b16 {%0,%1,%2,%3},[%4];"
                 : "=r"(r[0]), "=r"(r[1]), "=r"(r[2]), "=r"(r[3]) : "r"(addr));
}

__device__ __forceinline__ void mma16816(float* c, const uint32_t* a, const uint32_t* b) {
    asm volatile(
        "mma.sync.aligned.m16n8k16.row.col.f32.f16.f16.f32 "
        "{%0,%1,%2,%3},{%4,%5,%6,%7},{%8,%9},{%0,%1,%2,%3};"
        : "+f"(c[0]), "+f"(c[1]), "+f"(c[2]), "+f"(c[3])
        : "r"(a[0]), "r"(a[1]), "r"(a[2]), "r"(a[3]), "r"(b[0]), "r"(b[1]));
}

#define MBARRIER_INIT(addr, cnt) \
    asm volatile("mbarrier.init.shared.b64 [%0], %1;" :: "r"(addr), "r"(cnt) : "memory")
#define MBARRIER_ARRIVE(addr) \
    asm volatile("mbarrier.arrive.shared.b64 _, [%0];" :: "r"(addr) : "memory")

__device__ __forceinline__ void mbar_wait_parity(uint32_t mbar, uint32_t parity) {
    uint32_t done;
    asm volatile(
        "{\n\t.reg .pred p;\n\t"
        "mbarrier.try_wait.parity.acquire.cta.shared::cta.b64 p, [%1], %2;\n\t"
        "selp.b32 %0, 1, 0, p;\n\t}"
        : "=r"(done) : "r"(mbar), "r"(parity) : "memory");
    if (!done) {
        asm volatile(
            "{\n\t.reg .pred P1;\n\t"
            "WL_%=:\n\t"
            "mbarrier.try_wait.parity.acquire.cta.shared::cta.b64 P1, [%0], %1, 0x989680;\n\t"
            "@P1 bra.uni WD_%=;\n\t"
            "bra.uni WL_%=;\n\t"
            "WD_%=:\n\t}"
            :: "r"(mbar), "r"(parity) : "memory");
    }
}

__device__ __forceinline__ void bulk_ld(uint32_t dst, const void* src, uint32_t bytes, uint32_t mbar) {
    asm volatile(
        "cp.async.bulk.shared::cluster.global.mbarrier::complete_tx::bytes [%0], [%1], %2, [%3];"
        :: "r"(dst), "l"(src), "r"(bytes), "r"(mbar) : "memory");
}

__device__ __forceinline__ float tanh_fast(float x) {
    float y; asm("tanh.approx.f32 %0, %1;" : "=f"(y) : "f"(x)); return y;
}

__device__ __forceinline__ uint32_t pack_h2(float x, float y) {
    __half2 h = __floats2half2_rn(x, y);
    return *reinterpret_cast<uint32_t*>(&h);
}

// ---------------- Kernel 1: fp32 -> tiled/swizzled fp16 (V and U merged) --
// blk < 4096: V tile (b*128 + sblk*16 + kt), 256x64. blk >= 4096: U tile 128x64.
__global__ void cvt_kernel(const float* __restrict__ V, const float* __restrict__ U) {
    const int blk = blockIdx.x;
    const int t = threadIdx.x;
    if (blk < 4096) {
        const int b  = blk >> 7;
        const int sb = (blk >> 4) & 7;
        const int kt = blk & 15;
        const float* src = V + ((size_t)b * S_ + sb * 256) * VLEN + kt * 64;
        char* dst = reinterpret_cast<char*>(g_Vh) + (((size_t)(b * 8 + sb) * 16 + kt) << 15);
        const int rowq = t >> 2;       // 0..63
        const int cq   = t & 3;        // 16-float column group
        #pragma unroll
        for (int p = 0; p < 4; ++p) {
            const int row = rowq + p * 64;
            const float4* s4 = reinterpret_cast<const float4*>(src + (size_t)row * VLEN + cq * 16);
            #pragma unroll
            for (int j = 0; j < 2; ++j) {
                const float4 f0 = s4[j * 2], f1 = s4[j * 2 + 1];
                uint4 hv;
                hv.x = pack_h2(f0.x, f0.y); hv.y = pack_h2(f0.z, f0.w);
                hv.z = pack_h2(f1.x, f1.y); hv.w = pack_h2(f1.z, f1.w);
                uint32_t off = (row << 7) + cq * 32 + j * 16;
                off ^= (off >> 3) & 0x70;
                *reinterpret_cast<uint4*>(dst + off) = hv;
            }
        }
    } else {
        const int ublk = blk - 4096;   // 0..127
        const int nb = ublk >> 4;
        const int kt = ublk & 15;
        const float* src = U + (size_t)(nb * 128) * VLEN + kt * 64;
        char* dst = reinterpret_cast<char*>(g_Uh) + ((size_t)ublk << 14);
        const int row = t >> 1;        // 0..127
        const int cq  = t & 1;         // 32-float column group
        const float4* s4 = reinterpret_cast<const float4*>(src + (size_t)row * VLEN + cq * 32);
        #pragma unroll
        for (int j = 0; j < 4; ++j) {
            const float4 f0 = s4[j * 2], f1 = s4[j * 2 + 1];
            uint4 hv;
            hv.x = pack_h2(f0.x, f0.y); hv.y = pack_h2(f0.z, f0.w);
            hv.z = pack_h2(f1.x, f1.y); hv.w = pack_h2(f1.z, f1.w);
            uint32_t off = (row << 7) + cq * 64 + j * 16;
            off ^= (off >> 3) & 0x70;
            *reinterpret_cast<uint4*>(dst + off) = hv;
        }
    }
}

// ---------------- Kernel 2: h_proj[b,d] = h[b]·W_w[d] + W_b[d] ------------
__global__ void hproj_kernel(const float* __restrict__ h,
                             const float* __restrict__ Ww,
                             const float* __restrict__ Wb) {
    int w = (blockIdx.x * blockDim.x + threadIdx.x) >> 5;
    int lane = threadIdx.x & 31;
    int b = w >> 10;
    int d = w & 1023;
    if (b >= B_) return;
    const float* hv = h + (size_t)b * HLEN;
    const float* wr = Ww + (size_t)d * HLEN;
    float acc = 0.f;
    #pragma unroll 8
    for (int v = lane; v < HLEN; v += 32) acc += hv[v] * wr[v];
    #pragma unroll
    for (int o = 16; o; o >>= 1) acc += __shfl_xor_sync(0xffffffffu, acc, o);
    if (lane == 0) g_hp[b * HID + d] = acc + Wb[d];
}

// ---------------- Kernel 3: fused e = w·tanh(hp + V U^T) ----------------
// Bulk-DMA mbarrier pipeline, 3 stages. 512 threads (16 warps: 8(M) x 2(N)).
// Tile M=256(s), N=128(d), K=64. grid=(8, 32). hp/ww staged in smem.
#define NTILES 128
#define STAGE_SZ 49152
#define SMEM_STAGE0 12288
#define E_SMEM (SMEM_STAGE0 + 3 * STAGE_SZ)   // 159744

__global__ void __launch_bounds__(512, 1) e_kernel(const float* __restrict__ ww) {
    extern __shared__ char smem[];
    const uint32_t sbase = smem_u32(smem);
    float* e_red = reinterpret_cast<float*>(smem + 64);     // 256 floats
    float* sm_hp = reinterpret_cast<float*>(smem + 1088);   // 1024 floats
    float* sm_ww = reinterpret_cast<float*>(smem + 5184);   // 1024 floats

    const int tid  = threadIdx.x;
    const int lane = tid & 31;
    const int warp = tid >> 5;
    const int wm = warp & 7;     // 0..7 -> 32 rows each (256 total)
    const int wn = warp >> 3;    // 0..1 -> 64 cols each
    const int b  = blockIdx.y;
    const int sb = blockIdx.x;   // s-block of 256

    const uint32_t full0  = sbase;        // 3 x 8B
    const uint32_t empty0 = sbase + 24;   // 3 x 8B

    if (tid == 0) {
        #pragma unroll
        for (int s = 0; s < 3; s++) {
            MBARRIER_INIT(full0 + s * 8, 1);
            MBARRIER_INIT(empty0 + s * 8, 16);
        }
    }
    if (tid < 256) {
        e_red[tid] = 0.f;
        const float4 h4 = reinterpret_cast<const float4*>(g_hp + b * HID)[tid];
        reinterpret_cast<float4*>(sm_hp)[tid] = h4;
        const float4 w4 = reinterpret_cast<const float4*>(ww)[tid];
        reinterpret_cast<float4*>(sm_ww)[tid] = w4;
    }
    __syncthreads();

    const char* Ab = reinterpret_cast<const char*>(g_Vh) + (((size_t)(b * 8 + sb) * 16) << 15);
    const char* Bb = reinterpret_cast<const char*>(g_Uh);

    // ---- producer: single thread, 2 bulk copies per tile ----
    auto produce = [&](int c) {
        const int s = c % 3, r = c / 3;
        if (r >= 1) mbar_wait_parity(empty0 + s * 8, (uint32_t)(r - 1) & 1);
        const uint32_t mb = full0 + s * 8;
        asm volatile("mbarrier.arrive.expect_tx.shared.b64 _, [%0], %1;"
                     :: "r"(mb), "r"(49152u) : "memory");
        const uint32_t dstA = sbase + SMEM_STAGE0 + s * STAGE_SZ;
        bulk_ld(dstA,         Ab + ((size_t)(c & 15) << 15), 32768u, mb);
        bulk_ld(dstA + 32768, Bb + ((size_t)((c >> 4) * 16 + (c & 15)) << 14), 16384u, mb);
    };

    if (tid == 0) { produce(0); produce(1); }

    // ---- ldmatrix address precompute ----
    uint32_t abase[2], axor[2];
    #pragma unroll
    for (int mf = 0; mf < 2; ++mf) {
        const uint32_t row = wm * 32 + mf * 16 + (lane & 15);
        abase[mf] = row << 7;
        axor[mf]  = (row & 7) << 4;
    }
    const uint32_t acol0 = (lane >> 4) << 4;
    uint32_t bbase[4], bxor[4];
    #pragma unroll
    for (int nf2 = 0; nf2 < 4; ++nf2) {
        const uint32_t row = wn * 64 + nf2 * 16 + ((lane >> 4) << 3) + (lane & 7);
        bbase[nf2] = row << 7;
        bxor[nf2]  = (row & 7) << 4;
    }
    const uint32_t bcol0 = ((lane >> 3) & 1) << 4;

    float acc[2][8][4] = {};
    float e_part[4] = {0.f, 0.f, 0.f, 0.f};

    for (int t = 0; t < NTILES; ++t) {
        if (tid == 0 && t + 2 < NTILES) produce(t + 2);

        mbar_wait_parity(full0 + (t % 3) * 8, (uint32_t)(t / 3) & 1);

        const uint32_t stg  = sbase + SMEM_STAGE0 + (t % 3) * STAGE_SZ;
        const uint32_t stgB = stg + 32768;

        #pragma unroll
        for (int ks = 0; ks < 4; ++ks) {
            const uint32_t kcol = (uint32_t)ks << 5;
            uint32_t a[2][4];
            #pragma unroll
            for (int mf = 0; mf < 2; ++mf)
                ldsm_x4(a[mf], stg + abase[mf] + ((kcol + acol0) ^ axor[mf]));
            uint32_t bb[4][4];
            #pragma unroll
            for (int nf2 = 0; nf2 < 4; ++nf2)
                ldsm_x4(bb[nf2], stgB + bbase[nf2] + ((kcol + bcol0) ^ bxor[nf2]));
            #pragma unroll
            for (int mf = 0; mf < 2; ++mf)
                #pragma unroll
                for (int nf = 0; nf < 8; ++nf)
                    mma16816(acc[mf][nf], a[mf], &bb[nf >> 1][(nf & 1) * 2]);
        }

        if (lane == 0) MBARRIER_ARRIVE(empty0 + (t % 3) * 8);

        if ((t & 15) == 15) {
            // ---- fold tanh + w_w dot on this 128-col n-block, reset acc ----
            const int n0 = (t >> 4) << 7;
            const int cb = (n0 + wn * 64) >> 1;  // float2 index base
            const float2* hp2 = reinterpret_cast<const float2*>(sm_hp);
            const float2* ww2 = reinterpret_cast<const float2*>(sm_ww);
            #pragma unroll
            for (int nf = 0; nf < 8; ++nf) {
                const int ci = cb + nf * 4 + (lane & 3);
                const float2 hh = hp2[ci];
                const float2 wv = ww2[ci];
                #pragma unroll
                for (int mf = 0; mf < 2; ++mf) {
                    e_part[mf * 2 + 0] += tanh_fast(acc[mf][nf][0] + hh.x) * wv.x
                                        + tanh_fast(acc[mf][nf][1] + hh.y) * wv.y;
                    e_part[mf * 2 + 1] += tanh_fast(acc[mf][nf][2] + hh.x) * wv.x
                                        + tanh_fast(acc[mf][nf][3] + hh.y) * wv.y;
                    acc[mf][nf][0] = 0.f; acc[mf][nf][1] = 0.f;
                    acc[mf][nf][2] = 0.f; acc[mf][nf][3] = 0.f;
                }
            }
        }
    }

    // reduce over the 4 lanes sharing each row
    #pragma unroll
    for (int i = 0; i < 4; i++) {
        e_part[i] += __shfl_xor_sync(0xffffffffu, e_part[i], 1);
        e_part[i] += __shfl_xor_sync(0xffffffffu, e_part[i], 2);
    }
    if ((lane & 3) == 0) {
        #pragma unroll
        for (int i = 0; i < 4; i++) {
            const int r = wm * 32 + (i >> 1) * 16 + (i & 1) * 8 + (lane >> 2);
            atomicAdd(&e_red[r], e_part[i]);
        }
    }
    __syncthreads();
    if (tid < 256)
        g_e[(size_t)b * S_ + sb * 256 + tid] = e_red[tid];
}

// ---------------- Kernel 4: softmax over S (warp-shuffle, 1024 thr) -------
__global__ void __launch_bounds__(1024) softmax_kernel() {
    const int b = blockIdx.x;
    float* row = g_e + (size_t)b * S_;
    const int t = threadIdx.x, lane = t & 31, warp = t >> 5;
    __shared__ float red[32];

    const float2 v = reinterpret_cast<float2*>(row)[t];
    float m = fmaxf(v.x, v.y);
    #pragma unroll
    for (int o = 16; o; o >>= 1) m = fmaxf(m, __shfl_xor_sync(0xffffffffu, m, o));
    if (lane == 0) red[warp] = m;
    __syncthreads();
    if (warp == 0) {
        float x = red[lane];
        #pragma unroll
        for (int o = 16; o; o >>= 1) x = fmaxf(x, __shfl_xor_sync(0xffffffffu, x, o));
        red[lane] = x;
    }
    __syncthreads();
    m = red[0];
    __syncthreads();

    const float e0 = __expf(v.x - m), e1 = __expf(v.y - m);
    float s = e0 + e1;
    #pragma unroll
    for (int o = 16; o; o >>= 1) s += __shfl_xor_sync(0xffffffffu, s, o);
    if (lane == 0) red[warp] = s;
    __syncthreads();
    if (warp == 0) {
        float x = red[lane];
        #pragma unroll
        for (int o = 16; o; o >>= 1) x += __shfl_xor_sync(0xffffffffu, x, o);
        red[lane] = x;
    }
    __syncthreads();
    const float inv = 1.f / red[0];
    reinterpret_cast<float2*>(row)[t] = make_float2(e0 * inv, e1 * inv);
}

// ---------------- Kernel 5: out partials (tiled fp16 V, 8 s-chunks) -------
// grid (2, B, 8), 256 threads; each thread owns one half2 column, one 256-row s-block.
__global__ void out_part_kernel() {
    const int vc = blockIdx.x, b = blockIdx.y, sblk = blockIdx.z;
    const int v2 = vc * 256 + threadIdx.x;     // half2 col 0..511
    const int kt = v2 >> 5;                    // 64-col tile index
    const uint32_t coff = (v2 & 31) << 2;
    const float* beta = g_e + (size_t)b * S_ + sblk * 256;
    const char* tile = reinterpret_cast<const char*>(g_Vh)
                     + (((size_t)(b * 8 + sblk) * 16 + kt) << 15);

    float ax = 0.f, ay = 0.f;
    #pragma unroll 8
    for (int r = 0; r < 256; ++r) {
        uint32_t off = (r << 7) + coff;
        off ^= (off >> 3) & 0x70;
        const float2 vv = __half22float2(*reinterpret_cast<const __half2*>(tile + off));
        const float bt = beta[r];
        ax += bt * vv.x;
        ay += bt * vv.y;
    }
    float2* dst = reinterpret_cast<float2*>(g_part) + ((size_t)sblk * B_ + b) * (VLEN / 2) + v2;
    *dst = make_float2(ax, ay);
}

// ---------------- Kernel 6: reduce partials --------------------------------
__global__ void out_reduce_kernel(float* __restrict__ out) {
    int i = blockIdx.x * 256 + threadIdx.x;
    const int stride = B_ * VLEN;
    float s = 0.f;
    #pragma unroll
    for (int c = 0; c < 8; ++c) s += g_part[(size_t)c * stride + i];
    out[i] = s;
}

// ---------------- Launch ----------------
extern "C" void kernel_launch(void* const* d_in, const int* in_sizes, int n_in,
                              void* d_out, int out_size) {
    const float* h   = (const float*)d_in[0];   // [B, HLEN]
    const float* V   = (const float*)d_in[1];   // [B, S, VLEN]
    const float* W_w = (const float*)d_in[2];   // [HID, HLEN]
    const float* W_b = (const float*)d_in[3];   // [HID]
    const float* U_w = (const float*)d_in[4];   // [HID, VLEN]
    const float* w_w = (const float*)d_in[5];   // [HID]
    float* out = (float*)d_out;                 // [B, VLEN]

    cudaFuncSetAttribute(e_kernel, cudaFuncAttributeMaxDynamicSharedMemorySize, E_SMEM);

    // 1. fp32 -> tiled/swizzled fp16 (V + U in one launch)
    cvt_kernel<<<4096 + 128, 256>>>(V, U_w);
    // 2. h_proj
    hproj_kernel<<<(B_ * HID) / 8, 256>>>(h, W_w, W_b);
    // 3. fused e scores (bulk-DMA mbarrier pipelined HMMA, 3 stages)
    {
        dim3 grid(8, B_);
        e_kernel<<<grid, 512, E_SMEM>>>(w_w);
    }
    // 4. softmax
    softmax_kernel<<<B_, 1024>>>();
    // 5. weighted sum partials (tiled fp16 V, 8 s-chunks)
    {
        dim3 grid(2, B_, 8);
        out_part_kernel<<<grid, 256>>>();
    }
    // 6. reduce
    out_reduce_kernel<<<(B_ * VLEN) / 256, 256>>>(out);
}